// round 12
// baseline (speedup 1.0000x reference)
#include <cuda_runtime.h>
#include <cuda_bf16.h>
#include <cuda_fp16.h>

// FeaturesLinear: out[b,:] = sum_{t in segment b} user_W[fid[t],:] * rating_W[ridx[t],:]
//                           + item_W[item_ids[b],:] + bias
// Model (R10/R11 evidence): fp32 gathers are pinned at the LTS sector-request
// cap (~196 sectors/cyc == 192-slice limit) -> hard floor ~35us. The fp16
// mirror halves sectors (floor ~18us) but R10's K2 ran 38us with NOTHING
// saturated -> per-warp serialization (ffs->shfl->LDG chain, 1 segment/warp).
// This round: K1 fp32->fp16 mirror (unchanged), K2 processes TWO segments per
// warp with a fused interleaved scan (two independent gather chains per
// iteration) to double per-warp MLP. Accumulation stays fp32.

#define HIST 50
#define DVEC 32            // 128 dims / 4 per lane
#define THREADS 128
#define NU 100001          // NUM_ITEMS + 1
#define NU4 (NU * 32)

// fp16 mirror of user_W: NU rows x 128 halves = 25.6 MB (static scratch).
__device__ __align__(16) uint2 g_uW_h[NU * 32];

__global__ __launch_bounds__(256)
void convert_userW_kernel(const float4* __restrict__ userW)
{
    const int stride = gridDim.x * blockDim.x;
    for (int i = blockIdx.x * blockDim.x + threadIdx.x; i < NU4; i += stride) {
        const float4 v = __ldg(&userW[i]);
        const __half2 a = __floats2half2_rn(v.x, v.y);
        const __half2 b = __floats2half2_rn(v.z, v.w);
        uint2 o;
        o.x = *reinterpret_cast<const unsigned*>(&a);
        o.y = *reinterpret_cast<const unsigned*>(&b);
        g_uW_h[i] = o;
    }
}

__device__ __forceinline__ void acc_h4(float4& p, uint2 raw)
{
    const float2 f01 = __half22float2(*reinterpret_cast<const __half2*>(&raw.x));
    const float2 f23 = __half22float2(*reinterpret_cast<const __half2*>(&raw.y));
    p.x += f01.x; p.y += f01.y; p.z += f23.x; p.w += f23.y;
}

__global__ __launch_bounds__(THREADS, 8)
void features_linear_kernel(const int*    __restrict__ fids,      // [T]
                            const float*  __restrict__ ratings,   // [T]
                            const int*    __restrict__ segs,      // [T]
                            const int*    __restrict__ item_ids,  // [B]
                            const float4* __restrict__ ratingW,   // [10, 32]
                            const float4* __restrict__ itemW,     // [Ni, 32]
                            const float4* __restrict__ bias,      // [32]
                            float4*       __restrict__ out,       // [B, 32]
                            int batch)
{
    __shared__ float4 s_rw[10 * DVEC];
    __shared__ float4 s_bias[DVEC];

    for (int i = threadIdx.x; i < 10 * DVEC; i += THREADS) s_rw[i] = ratingW[i];
    if (threadIdx.x < DVEC) s_bias[threadIdx.x] = bias[threadIdx.x];
    __syncthreads();

    const int gwarp = (blockIdx.x * THREADS + threadIdx.x) >> 5;
    const int lane  = threadIdx.x & 31;

    const int segA = gwarp * 2;
    const int segB = segA + 1;
    if (segA >= batch) return;
    const bool hasB = (segB < batch);

    const int baseA = segA * HIST;
    const int baseB = segB * HIST;
    const bool lane2 = (lane < HIST - 32);

    // ---- Front-batched loads for both segments + both epilogue gathers ----
    int   fa0 = __ldg(&fids[baseA + lane]);
    float ra0 = __ldg(&ratings[baseA + lane]);
    int   fa1 = 0;  float ra1 = 0.0f;
    if (lane2) { fa1 = __ldg(&fids[baseA + 32 + lane]); ra1 = __ldg(&ratings[baseA + 32 + lane]); }

    int   fb0 = 0;  float rb0 = 0.0f;
    int   fb1 = 0;  float rb1 = 0.0f;
    if (hasB) {
        fb0 = __ldg(&fids[baseB + lane]);
        rb0 = __ldg(&ratings[baseB + lane]);
        if (lane2) { fb1 = __ldg(&fids[baseB + 32 + lane]); rb1 = __ldg(&ratings[baseB + 32 + lane]); }
    }

    const int rowA = __ldg(&segs[baseA]);
    const float4 itA = __ldg(&itemW[(size_t)__ldg(&item_ids[rowA]) * DVEC + lane]);
    int rowB = 0;
    float4 itB = make_float4(0.f, 0.f, 0.f, 0.f);
    if (hasB) {
        rowB = __ldg(&segs[baseB]);
        itB  = __ldg(&itemW[(size_t)__ldg(&item_ids[rowB]) * DVEC + lane]);
    }

    int rxa0 = min(max(__float2int_rn((ra0 - 0.5f) * 2.0f), 0), 9);
    int rxa1 = 15;
    if (lane2) rxa1 = min(max(__float2int_rn((ra1 - 0.5f) * 2.0f), 0), 9);
    int rxb0 = 15, rxb1 = 15;                  // sentinels if !hasB
    if (hasB) {
        rxb0 = min(max(__float2int_rn((rb0 - 0.5f) * 2.0f), 0), 9);
        if (lane2) rxb1 = min(max(__float2int_rn((rb1 - 0.5f) * 2.0f), 0), 9);
    }

    const uint2* __restrict__ uWh = g_uW_h;
    float4 accA = make_float4(0.f, 0.f, 0.f, 0.f);
    float4 accB = make_float4(0.f, 0.f, 0.f, 0.f);

    #pragma unroll
    for (int rx = 0; rx < 10; rx++) {
        unsigned a0 = __ballot_sync(0xffffffffu, rxa0 == rx);
        unsigned a1 = __ballot_sync(0xffffffffu, rxa1 == rx);
        unsigned b0 = __ballot_sync(0xffffffffu, rxb0 == rx);
        unsigned b1 = __ballot_sync(0xffffffffu, rxb1 == rx);

        float4 pA = make_float4(0.f, 0.f, 0.f, 0.f);
        float4 pB = make_float4(0.f, 0.f, 0.f, 0.f);

        // Fused interleaved scan: one gather from A and one from B per
        // iteration — two independent ffs/shfl/LDG chains in flight.
        while (a0 | b0) {
            if (a0) {
                const int i = __ffs(a0) - 1;  a0 &= a0 - 1;
                const int f = __shfl_sync(0xffffffffu, fa0, i);
                acc_h4(pA, __ldg(&uWh[((size_t)f << 5) + lane]));
            }
            if (b0) {
                const int i = __ffs(b0) - 1;  b0 &= b0 - 1;
                const int f = __shfl_sync(0xffffffffu, fb0, i);
                acc_h4(pB, __ldg(&uWh[((size_t)f << 5) + lane]));
            }
        }
        while (a1 | b1) {
            if (a1) {
                const int i = __ffs(a1) - 1;  a1 &= a1 - 1;
                const int f = __shfl_sync(0xffffffffu, fa1, i);
                acc_h4(pA, __ldg(&uWh[((size_t)f << 5) + lane]));
            }
            if (b1) {
                const int i = __ffs(b1) - 1;  b1 &= b1 - 1;
                const int f = __shfl_sync(0xffffffffu, fb1, i);
                acc_h4(pB, __ldg(&uWh[((size_t)f << 5) + lane]));
            }
        }

        const float4 s = s_rw[rx * DVEC + lane];
        accA.x = fmaf(pA.x, s.x, accA.x);  accB.x = fmaf(pB.x, s.x, accB.x);
        accA.y = fmaf(pA.y, s.y, accA.y);  accB.y = fmaf(pB.y, s.y, accB.y);
        accA.z = fmaf(pA.z, s.z, accA.z);  accB.z = fmaf(pB.z, s.z, accB.z);
        accA.w = fmaf(pA.w, s.w, accA.w);  accB.w = fmaf(pB.w, s.w, accB.w);
    }

    const float4 bz = s_bias[lane];
    float4 oA;
    oA.x = accA.x + itA.x + bz.x;
    oA.y = accA.y + itA.y + bz.y;
    oA.z = accA.z + itA.z + bz.z;
    oA.w = accA.w + itA.w + bz.w;
    out[(size_t)rowA * DVEC + lane] = oA;

    if (hasB) {
        float4 oB;
        oB.x = accB.x + itB.x + bz.x;
        oB.y = accB.y + itB.y + bz.y;
        oB.z = accB.z + itB.z + bz.z;
        oB.w = accB.w + itB.w + bz.w;
        out[(size_t)rowB * DVEC + lane] = oB;
    }
}

extern "C" void kernel_launch(void* const* d_in, const int* in_sizes, int n_in,
                              void* d_out, int out_size)
{
    const int*    fids     = (const int*)   d_in[0];
    const float*  ratings  = (const float*) d_in[1];
    const int*    segs     = (const int*)   d_in[2];
    const int*    item_ids = (const int*)   d_in[3];
    const float4* userW    = (const float4*)d_in[4];
    const float4* ratingW  = (const float4*)d_in[5];
    const float4* itemW    = (const float4*)d_in[6];
    const float4* bias     = (const float4*)d_in[7];
    float4*       out      = (float4*)      d_out;

    const int batch = in_sizes[3];                       // item_ids count
    const int warps = (batch + 1) / 2;                   // 2 segments per warp
    const int blocks = (warps * 32 + THREADS - 1) / THREADS;

    convert_userW_kernel<<<4096, 256>>>(userW);
    features_linear_kernel<<<blocks, THREADS>>>(
        fids, ratings, segs, item_ids, ratingW, itemW, bias, out, batch);
}

// round 13
// speedup vs baseline: 1.4124x; 1.4124x over previous
#include <cuda_runtime.h>
#include <cuda_fp16.h>

// FeaturesLinear: out[b,:] = sum_t user_W[fid]*rating_W[rx] + item_W[item_ids[b]] + bias
// K1: fp32 -> fp16 mirror of user_W (static scratch, 25.6 MB).
// K2: paired-row gather. fp16 row = 256B, so one warp-wide LDG.128 (512B)
//     fetches rows for TWO segments (half-warp each). Fixed unrolled 50-iter
//     loop, branch-free; one width-16 shfl broadcasts packed fid|rx per half.
//     HFMA2 half2 accumulation flushed to fp32 every 8 iters.

#define HIST 50
#define THREADS 128
#define NU 100001          // NUM_ITEMS + 1
#define NU4 (NU * 32)
#define FULL 0xffffffffu

// fp16 mirror of user_W: NU rows x 128 halves = 25.6 MB.
__device__ __align__(16) uint2 g_uW_h[NU * 32];

__global__ __launch_bounds__(256)
void convert_userW_kernel(const float4* __restrict__ userW)
{
    const int stride = gridDim.x * blockDim.x;
    for (int i = blockIdx.x * blockDim.x + threadIdx.x; i < NU4; i += stride) {
        const float4 v = __ldcs(&userW[i]);     // streaming read: don't evict mirror
        const __half2 a = __floats2half2_rn(v.x, v.y);
        const __half2 b = __floats2half2_rn(v.z, v.w);
        uint2 o;
        o.x = *reinterpret_cast<const unsigned*>(&a);
        o.y = *reinterpret_cast<const unsigned*>(&b);
        g_uW_h[i] = o;
    }
}

__device__ __forceinline__ __half2 u2h(unsigned v) {
    return *reinterpret_cast<const __half2*>(&v);
}

__global__ __launch_bounds__(THREADS, 10)
void features_linear_kernel(const int*    __restrict__ fids,      // [T]
                            const float*  __restrict__ ratings,   // [T]
                            const int*    __restrict__ segs,      // [T]
                            const int*    __restrict__ item_ids,  // [B]
                            const float4* __restrict__ ratingW,   // [10, 32]
                            const float4* __restrict__ itemW,     // [Ni, 32]
                            const float4* __restrict__ bias,      // [32]
                            float4*       __restrict__ out,       // [B, 32]
                            int batch)
{
    // fp16 rating table: [rx][k] = halves 8k..8k+7 of rating row rx (2.5 KB).
    __shared__ uint4  s_rw_h[10 * 16];
    __shared__ float4 s_bias[32];

    for (int j = threadIdx.x; j < 160; j += THREADS) {
        const int rx = j >> 4, kk = j & 15;
        const float4 f0 = ratingW[rx * 32 + 2 * kk];
        const float4 f1 = ratingW[rx * 32 + 2 * kk + 1];
        const __half2 h0 = __floats2half2_rn(f0.x, f0.y);
        const __half2 h1 = __floats2half2_rn(f0.z, f0.w);
        const __half2 h2 = __floats2half2_rn(f1.x, f1.y);
        const __half2 h3 = __floats2half2_rn(f1.z, f1.w);
        uint4 w;
        w.x = *reinterpret_cast<const unsigned*>(&h0);
        w.y = *reinterpret_cast<const unsigned*>(&h1);
        w.z = *reinterpret_cast<const unsigned*>(&h2);
        w.w = *reinterpret_cast<const unsigned*>(&h3);
        s_rw_h[j] = w;
    }
    if (threadIdx.x < 32) s_bias[threadIdx.x] = bias[threadIdx.x];
    __syncthreads();

    const int gwarp = (blockIdx.x * THREADS + threadIdx.x) >> 5;
    const int lane  = threadIdx.x & 31;
    const int half  = lane >> 4;          // 0: segment A, 1: segment B
    const int k     = lane & 15;          // 16B chunk within the 256B fp16 row

    const int segA = gwarp * 2;
    if (segA >= batch) return;
    const bool hasB = (segA + 1 < batch);
    const bool mine = (half == 0) || hasB;

    const int mybase = (half ? segA + 1 : segA) * HIST;

    // ---- Prefetch this half's 50 (fid, rx) pairs, packed, 4 regs/lane ----
    int c[4];
    #pragma unroll
    for (int r = 0; r < 4; r++) {
        const int idx = r * 16 + k;
        int f = 0, rx = 0;
        if (mine && idx < HIST) {
            f = __ldg(&fids[mybase + idx]);
            const float rr = __ldg(&ratings[mybase + idx]);
            rx = min(max(__float2int_rn((rr - 0.5f) * 2.0f), 0), 9);
        }
        c[r] = f | (rx << 20);
    }

    // ---- Epilogue loads hoisted ----
    const int rowA = __ldg(&segs[segA * HIST]);
    const int rowB = hasB ? __ldg(&segs[(segA + 1) * HIST]) : 0;
    const int myrow = half ? rowB : rowA;
    const int iid = mine ? __ldg(&item_ids[myrow]) : 0;
    const float4 it0 = __ldg(&itemW[(size_t)iid * 32 + 2 * k]);
    const float4 it1 = __ldg(&itemW[(size_t)iid * 32 + 2 * k + 1]);

    const uint4* __restrict__ uW4 = reinterpret_cast<const uint4*>(g_uW_h);

    float  accf[8];
    #pragma unroll
    for (int j = 0; j < 8; j++) accf[j] = 0.0f;
    __half2 ah[4];
    const __half2 hz = __floats2half2_rn(0.0f, 0.0f);
    #pragma unroll
    for (int j = 0; j < 4; j++) ah[j] = hz;

    // ---- Main loop: 50 iterations, branch-free, fully unrolled.
    // One LDG.128 per iteration gathers one row for EACH half-warp. ----
    #pragma unroll
    for (int t = 0; t < HIST; t++) {
        const int r = t >> 4, s = t & 15;
        const int packed = __shfl_sync(FULL, c[r], s, 16);   // per-half broadcast
        const int fid = packed & 0xFFFFF;
        const int rx  = packed >> 20;

        const uint4 u = __ldg(&uW4[(size_t)fid * 16 + k]);
        const uint4 w = s_rw_h[rx * 16 + k];

        ah[0] = __hfma2(u2h(u.x), u2h(w.x), ah[0]);
        ah[1] = __hfma2(u2h(u.y), u2h(w.y), ah[1]);
        ah[2] = __hfma2(u2h(u.z), u2h(w.z), ah[2]);
        ah[3] = __hfma2(u2h(u.w), u2h(w.w), ah[3]);

        if ((t & 7) == 7 || t == HIST - 1) {     // compile-time: flush to fp32
            #pragma unroll
            for (int j = 0; j < 4; j++) {
                const float2 f = __half22float2(ah[j]);
                accf[2 * j]     += f.x;
                accf[2 * j + 1] += f.y;
                ah[j] = hz;
            }
        }
    }

    const float4 b0 = s_bias[2 * k];
    const float4 b1 = s_bias[2 * k + 1];
    if (mine) {
        float4 o0, o1;
        o0.x = accf[0] + it0.x + b0.x;
        o0.y = accf[1] + it0.y + b0.y;
        o0.z = accf[2] + it0.z + b0.z;
        o0.w = accf[3] + it0.w + b0.w;
        o1.x = accf[4] + it1.x + b1.x;
        o1.y = accf[5] + it1.y + b1.y;
        o1.z = accf[6] + it1.z + b1.z;
        o1.w = accf[7] + it1.w + b1.w;
        out[(size_t)myrow * 32 + 2 * k]     = o0;
        out[(size_t)myrow * 32 + 2 * k + 1] = o1;
    }
}

extern "C" void kernel_launch(void* const* d_in, const int* in_sizes, int n_in,
                              void* d_out, int out_size)
{
    const int*    fids     = (const int*)   d_in[0];
    const float*  ratings  = (const float*) d_in[1];
    const int*    segs     = (const int*)   d_in[2];
    const int*    item_ids = (const int*)   d_in[3];
    const float4* userW    = (const float4*)d_in[4];
    const float4* ratingW  = (const float4*)d_in[5];
    const float4* itemW    = (const float4*)d_in[6];
    const float4* bias     = (const float4*)d_in[7];
    float4*       out      = (float4*)      d_out;

    const int batch = in_sizes[3];                   // item_ids count
    const int pairs = (batch + 1) / 2;               // 2 segments per warp
    const int blocks = (pairs * 32 + THREADS - 1) / THREADS;

    convert_userW_kernel<<<4096, 256>>>(userW);
    features_linear_kernel<<<blocks, THREADS>>>(
        fids, ratings, segs, item_ids, ratingW, itemW, bias, out, batch);
}

// round 14
// speedup vs baseline: 2.1036x; 1.4894x over previous
#include <cuda_runtime.h>
#include <cuda_fp16.h>

// FeaturesLinear: out[b,:] = sum_t user_W[fid]*rating_W[rx] + item_W[item_ids[b]] + bias
// K1: fp32 -> fp16 mirror of user_W (static scratch, 25.6 MB).
// K2: ONE segment per warp, FIXED fully-unrolled 50-iter loop (loads are
//     control-independent -> ptxas batches them, unlike the mask-driven scan),
//     fp16 LDG.64 gathers (256B/row, 2 L1 wavefronts), one packed shfl
//     (fid|rx<<20), LDS.64 rating row, 2x HFMA2 per iter, fp32 flush every 8.
// This combines the proven-pipelining R1 loop shape with halved per-iteration
// cost everywhere (sectors, wavefronts, instructions).

#define HIST 50
#define THREADS 128
#define NU 100001          // NUM_ITEMS + 1
#define NU4 (NU * 32)
#define FULL 0xffffffffu

// fp16 mirror of user_W: NU rows x 128 halves = 25.6 MB. Row = 32 x uint2.
__device__ __align__(16) uint2 g_uW_h[NU * 32];

__global__ __launch_bounds__(256)
void convert_userW_kernel(const float4* __restrict__ userW)
{
    const int stride = gridDim.x * blockDim.x;
    for (int i = blockIdx.x * blockDim.x + threadIdx.x; i < NU4; i += stride) {
        const float4 v = __ldcs(&userW[i]);
        const __half2 a = __floats2half2_rn(v.x, v.y);
        const __half2 b = __floats2half2_rn(v.z, v.w);
        uint2 o;
        o.x = *reinterpret_cast<const unsigned*>(&a);
        o.y = *reinterpret_cast<const unsigned*>(&b);
        g_uW_h[i] = o;
    }
}

__device__ __forceinline__ __half2 u2h(unsigned v) {
    return *reinterpret_cast<const __half2*>(&v);
}

__global__ __launch_bounds__(THREADS, 10)
void features_linear_kernel(const int*    __restrict__ fids,      // [T]
                            const float*  __restrict__ ratings,   // [T]
                            const int*    __restrict__ segs,      // [T]
                            const int*    __restrict__ item_ids,  // [B]
                            const float4* __restrict__ ratingW,   // [10, 32]
                            const float4* __restrict__ itemW,     // [Ni, 32]
                            const float4* __restrict__ bias,      // [32]
                            float4*       __restrict__ out,       // [B, 32]
                            int batch)
{
    // fp16 rating table: row rx = 32 x uint2 (4 halves per lane), 2.5 KB.
    __shared__ uint2  s_rw[10 * 32];
    __shared__ float4 s_bias[32];

    for (int j = threadIdx.x; j < 10 * 32; j += THREADS) {
        const float4 f = ratingW[j];
        const __half2 a = __floats2half2_rn(f.x, f.y);
        const __half2 b = __floats2half2_rn(f.z, f.w);
        uint2 w;
        w.x = *reinterpret_cast<const unsigned*>(&a);
        w.y = *reinterpret_cast<const unsigned*>(&b);
        s_rw[j] = w;
    }
    if (threadIdx.x < 32) s_bias[threadIdx.x] = bias[threadIdx.x];
    __syncthreads();

    const int gwarp = (blockIdx.x * THREADS + threadIdx.x) >> 5;
    const int lane  = threadIdx.x & 31;
    if (gwarp >= batch) return;

    const int base = gwarp * HIST;

    // ---- Prefetch 50 (fid, rx) pairs packed into 2 regs/lane ----
    int c0, c1 = 0;
    {
        const int f = __ldg(&fids[base + lane]);
        const float r = __ldg(&ratings[base + lane]);
        const int rx = min(max(__float2int_rn((r - 0.5f) * 2.0f), 0), 9);
        c0 = f | (rx << 20);
    }
    if (lane < HIST - 32) {
        const int f = __ldg(&fids[base + 32 + lane]);
        const float r = __ldg(&ratings[base + 32 + lane]);
        const int rx = min(max(__float2int_rn((r - 0.5f) * 2.0f), 0), 9);
        c1 = f | (rx << 20);
    }

    // ---- Epilogue loads hoisted ----
    const int row = __ldg(&segs[base]);
    const float4 it = __ldg(&itemW[(size_t)__ldg(&item_ids[row]) * 32 + lane]);

    const uint2* __restrict__ uWh = g_uW_h;

    float accf[4] = {0.f, 0.f, 0.f, 0.f};
    const __half2 hz = __floats2half2_rn(0.0f, 0.0f);
    __half2 ah0 = hz, ah1 = hz;

    // ---- Main loop: fixed 50 iterations, fully unrolled, loads batchable ----
    #pragma unroll
    for (int t = 0; t < HIST; t++) {
        const int packed = (t < 32) ? __shfl_sync(FULL, c0, t)
                                    : __shfl_sync(FULL, c1, t - 32);
        const int fid = packed & 0xFFFFF;
        const int rx  = packed >> 20;

        const uint2 u = __ldg(&uWh[((size_t)fid << 5) + lane]);   // LDG.64, 256B/warp
        const uint2 w = s_rw[(rx << 5) + lane];                   // LDS.64

        ah0 = __hfma2(u2h(u.x), u2h(w.x), ah0);
        ah1 = __hfma2(u2h(u.y), u2h(w.y), ah1);

        if ((t & 7) == 7 || t == HIST - 1) {       // compile-time flush to fp32
            const float2 f0 = __half22float2(ah0);
            const float2 f1 = __half22float2(ah1);
            accf[0] += f0.x; accf[1] += f0.y;
            accf[2] += f1.x; accf[3] += f1.y;
            ah0 = hz; ah1 = hz;
        }
    }

    const float4 bz = s_bias[lane];
    float4 o;
    o.x = accf[0] + it.x + bz.x;
    o.y = accf[1] + it.y + bz.y;
    o.z = accf[2] + it.z + bz.z;
    o.w = accf[3] + it.w + bz.w;
    out[(size_t)row * 32 + lane] = o;
}

extern "C" void kernel_launch(void* const* d_in, const int* in_sizes, int n_in,
                              void* d_out, int out_size)
{
    const int*    fids     = (const int*)   d_in[0];
    const float*  ratings  = (const float*) d_in[1];
    const int*    segs     = (const int*)   d_in[2];
    const int*    item_ids = (const int*)   d_in[3];
    const float4* userW    = (const float4*)d_in[4];
    const float4* ratingW  = (const float4*)d_in[5];
    const float4* itemW    = (const float4*)d_in[6];
    const float4* bias     = (const float4*)d_in[7];
    float4*       out      = (float4*)      d_out;

    const int batch  = in_sizes[3];                 // item_ids count
    const int blocks = (batch * 32 + THREADS - 1) / THREADS;   // 1 warp/segment

    convert_userW_kernel<<<4096, 256>>>(userW);
    features_linear_kernel<<<blocks, THREADS>>>(
        fids, ratings, segs, item_ids, ratingW, itemW, bias, out, batch);
}

// round 15
// speedup vs baseline: 2.2459x; 1.0676x over previous
#include <cuda_runtime.h>
#include <cuda_fp16.h>

// FeaturesLinear: out[b,:] = sum_t user_W[fid]*rating_W[rx] + item_W[item_ids[b]] + bias
// K1: fp32 -> fp16 mirror of user_W (static scratch, 25.6 MB). Wide version:
//     2x float4 loads -> 1x uint4 store per iteration.
// K2: ONE segment per warp, FIXED fully-unrolled 50-iter loop (loads are
//     control-independent -> ptxas batches them), fp16 LDG.64 gathers
//     (256B/row), one packed shfl (fid|rx<<20), LDS.64 rating row, 2x HFMA2
//     per iter, fp32 flush every 8. 32-bit byte-offset addressing into the
//     25.6MB mirror (fits 32 bits) to trim the per-iter ALU chain.

#define HIST 50
#define THREADS 128
#define NU 100001          // NUM_ITEMS + 1
#define NU16 (NU * 16)     // uint4 count of the fp16 mirror
#define FULL 0xffffffffu

// fp16 mirror of user_W: NU rows x 128 halves = 25.6 MB. Row = 256 bytes.
__device__ __align__(16) uint2 g_uW_h[NU * 32];

__global__ __launch_bounds__(256)
void convert_userW_kernel(const float4* __restrict__ userW)
{
    uint4* __restrict__ dst = reinterpret_cast<uint4*>(g_uW_h);
    const int stride = gridDim.x * blockDim.x;
    for (int i = blockIdx.x * blockDim.x + threadIdx.x; i < NU16; i += stride) {
        const float4 v0 = __ldcs(&userW[2 * i]);
        const float4 v1 = __ldcs(&userW[2 * i + 1]);
        const __half2 a = __floats2half2_rn(v0.x, v0.y);
        const __half2 b = __floats2half2_rn(v0.z, v0.w);
        const __half2 c = __floats2half2_rn(v1.x, v1.y);
        const __half2 d = __floats2half2_rn(v1.z, v1.w);
        uint4 o;
        o.x = *reinterpret_cast<const unsigned*>(&a);
        o.y = *reinterpret_cast<const unsigned*>(&b);
        o.z = *reinterpret_cast<const unsigned*>(&c);
        o.w = *reinterpret_cast<const unsigned*>(&d);
        dst[i] = o;
    }
}

__device__ __forceinline__ __half2 u2h(unsigned v) {
    return *reinterpret_cast<const __half2*>(&v);
}

__global__ __launch_bounds__(THREADS, 10)
void features_linear_kernel(const int*    __restrict__ fids,      // [T]
                            const float*  __restrict__ ratings,   // [T]
                            const int*    __restrict__ segs,      // [T]
                            const int*    __restrict__ item_ids,  // [B]
                            const float4* __restrict__ ratingW,   // [10, 32]
                            const float4* __restrict__ itemW,     // [Ni, 32]
                            const float4* __restrict__ bias,      // [32]
                            float4*       __restrict__ out,       // [B, 32]
                            int batch)
{
    // fp16 rating table: row rx = 32 x uint2 (4 halves per lane), 2.5 KB.
    __shared__ uint2  s_rw[10 * 32];
    __shared__ float4 s_bias[32];

    for (int j = threadIdx.x; j < 10 * 32; j += THREADS) {
        const float4 f = ratingW[j];
        const __half2 a = __floats2half2_rn(f.x, f.y);
        const __half2 b = __floats2half2_rn(f.z, f.w);
        uint2 w;
        w.x = *reinterpret_cast<const unsigned*>(&a);
        w.y = *reinterpret_cast<const unsigned*>(&b);
        s_rw[j] = w;
    }
    if (threadIdx.x < 32) s_bias[threadIdx.x] = bias[threadIdx.x];
    __syncthreads();

    const int gwarp = (blockIdx.x * THREADS + threadIdx.x) >> 5;
    const int lane  = threadIdx.x & 31;
    if (gwarp >= batch) return;

    const int base = gwarp * HIST;

    // ---- Prefetch 50 (fid, rx) pairs packed into 2 regs/lane ----
    int c0, c1 = 0;
    {
        const int f = __ldg(&fids[base + lane]);
        const float r = __ldg(&ratings[base + lane]);
        const int rx = min(max(__float2int_rn((r - 0.5f) * 2.0f), 0), 9);
        c0 = f | (rx << 20);
    }
    if (lane < HIST - 32) {
        const int f = __ldg(&fids[base + 32 + lane]);
        const float r = __ldg(&ratings[base + 32 + lane]);
        const int rx = min(max(__float2int_rn((r - 0.5f) * 2.0f), 0), 9);
        c1 = f | (rx << 20);
    }

    // ---- Epilogue loads hoisted ----
    const int row = __ldg(&segs[base]);
    const float4 it = __ldg(&itemW[(size_t)__ldg(&item_ids[row]) * 32 + lane]);

    const char* __restrict__ uWb = reinterpret_cast<const char*>(g_uW_h);
    const unsigned laneoff = (unsigned)lane << 3;     // 8B per lane within row

    float accf[4] = {0.f, 0.f, 0.f, 0.f};
    const __half2 hz = __floats2half2_rn(0.0f, 0.0f);
    __half2 ah0 = hz, ah1 = hz;

    // ---- Main loop: fixed 50 iterations, fully unrolled, loads batchable ----
    #pragma unroll
    for (int t = 0; t < HIST; t++) {
        const int packed = (t < 32) ? __shfl_sync(FULL, c0, t)
                                    : __shfl_sync(FULL, c1, t - 32);
        const int fid = packed & 0xFFFFF;
        const int rx  = packed >> 20;

        // 32-bit byte offset into the 25.6MB mirror: fid*256 | lane*8.
        const unsigned off = ((unsigned)fid << 8) | laneoff;
        const uint2 u = __ldg(reinterpret_cast<const uint2*>(uWb + off)); // LDG.64
        const uint2 w = s_rw[(rx << 5) + lane];                            // LDS.64

        ah0 = __hfma2(u2h(u.x), u2h(w.x), ah0);
        ah1 = __hfma2(u2h(u.y), u2h(w.y), ah1);

        if ((t & 7) == 7 || t == HIST - 1) {       // compile-time flush to fp32
            const float2 f0 = __half22float2(ah0);
            const float2 f1 = __half22float2(ah1);
            accf[0] += f0.x; accf[1] += f0.y;
            accf[2] += f1.x; accf[3] += f1.y;
            ah0 = hz; ah1 = hz;
        }
    }

    const float4 bz = s_bias[lane];
    float4 o;
    o.x = accf[0] + it.x + bz.x;
    o.y = accf[1] + it.y + bz.y;
    o.z = accf[2] + it.z + bz.z;
    o.w = accf[3] + it.w + bz.w;
    out[(size_t)row * 32 + lane] = o;
}

extern "C" void kernel_launch(void* const* d_in, const int* in_sizes, int n_in,
                              void* d_out, int out_size)
{
    const int*    fids     = (const int*)   d_in[0];
    const float*  ratings  = (const float*) d_in[1];
    const int*    segs     = (const int*)   d_in[2];
    const int*    item_ids = (const int*)   d_in[3];
    const float4* userW    = (const float4*)d_in[4];
    const float4* ratingW  = (const float4*)d_in[5];
    const float4* itemW    = (const float4*)d_in[6];
    const float4* bias     = (const float4*)d_in[7];
    float4*       out      = (float4*)      d_out;

    const int batch  = in_sizes[3];                 // item_ids count
    const int blocks = (batch * 32 + THREADS - 1) / THREADS;   // 1 warp/segment

    convert_userW_kernel<<<2048, 256>>>(userW);
    features_linear_kernel<<<blocks, THREADS>>>(
        fids, ratings, segs, item_ids, ratingW, itemW, bias, out, batch);
}